// round 15
// baseline (speedup 1.0000x reference)
#include <cuda_runtime.h>
#include <cuda_fp16.h>
#include <math.h>

// Problem constants
#define Bz   64
#define Lz   512
#define Hz   256
#define GRID 128
#define NTH  512

#define EPITCH 68   // enc smem pitch in 4-byte words (272B rows, conflict-free)

// -------- device scratch --------
__device__ float  g_P[Lz * Bz * Hz];       // P / listH
__device__ __half g_enc[Lz * Bz * Hz];     // enc fp16 (CTA-local round trip)
__device__ float  g_WhT[Hz * Hz];          // WhT[k*256+j]
__device__ float  g_e4[3][128][32];        // energies: 128 groups of 4 l's, 128B stride, 3 bufs
__device__ unsigned long long g_l1[16 * 16];  // barrier level-1 counters (padded)
__device__ unsigned long long g_root = 0;     // barrier root counter

// -------- fast transcendentals (MUFU-based, ~2 ulp) --------
__device__ __forceinline__ float fsig(float x) {
    return __fdividef(1.f, 1.f + __expf(-x));
}
__device__ __forceinline__ float ftanh(float x) {
    return 1.f - __fdividef(2.f, __expf(2.f * x) + 1.f);
}

// -------- two-level grid barrier, split arrive/wait (monotonic) --------
__device__ __forceinline__ void gbar_arrive(unsigned long long& target) {
    __syncthreads();
    if (threadIdx.x == 0) {
        __threadfence();   // release (drains this CTA's RED/STG)
        unsigned long long a = atomicAdd(&g_l1[(blockIdx.x & 15) * 16], 1ULL);
        if ((a & 7ULL) == 7ULL) atomicAdd(&g_root, 1ULL);
        target = ((a >> 3) + 1ULL) * 16ULL;
    }
}
__device__ __forceinline__ void gbar_wait(unsigned long long target) {
    if (threadIdx.x == 0) {
        while (*((volatile unsigned long long*)&g_root) < target) { }
        __threadfence();   // acquire
    }
    __syncthreads();
}
__device__ __forceinline__ void gbar() {
    unsigned long long tgt = 0;
    gbar_arrive(tgt);
    gbar_wait(tgt);
}

// -------- cluster-scope mbarrier parity wait (acquire.cluster) --------
__device__ __forceinline__ void mbar_wait_cluster(unsigned mbar, unsigned parity) {
    unsigned done;
    do {
        asm volatile(
            "{\n\t.reg .pred p;\n\t"
            "mbarrier.try_wait.parity.acquire.cluster.shared::cta.b64 p, [%1], %2;\n\t"
            "selp.b32 %0, 1, 0, p;\n\t}"
            : "=r"(done) : "r"(mbar), "r"(parity) : "memory");
    } while (!done);
}

// -------- kernel 1: transpose Wh --------
__global__ void k_pre(const float* __restrict__ Wh) {
    int t = blockIdx.x * 256 + threadIdx.x;
    if (t < Hz * Hz) {
        int j = t >> 8, k = t & 255;
        g_WhT[k * 256 + j] = Wh[j * 256 + k];
    }
}

// -------- kernel 2: P = x@Wx^T + bx + bh  (128x64 tile, 8x4/thread) --------
__global__ void k_gemm(const float* __restrict__ x, const float* __restrict__ Wx,
                       const float* __restrict__ bx, const float* __restrict__ bh) {
    __shared__ float As[32][132];
    __shared__ float Bs[32][68];
    const int bm = blockIdx.y;
    const int bn = blockIdx.x;
    const int tid = threadIdx.x;
    const int ty = tid >> 4, tx = tid & 15;

    float acc[8][4];
#pragma unroll
    for (int i = 0; i < 8; i++)
#pragma unroll
        for (int j = 0; j < 4; j++) acc[i][j] = 0.f;

    for (int kt = 0; kt < 256; kt += 32) {
#pragma unroll
        for (int i = 0; i < 4; i++) {
            int idx = tid + i * 256;
            int r = idx >> 3, c4 = idx & 7;
            int m = bm * 128 + r;
            int l = m >> 6, b = m & 63;
            float4 v = *(const float4*)&x[((size_t)b * 512 + l) * 256 + kt + c4 * 4];
            As[c4 * 4 + 0][r] = v.x;
            As[c4 * 4 + 1][r] = v.y;
            As[c4 * 4 + 2][r] = v.z;
            As[c4 * 4 + 3][r] = v.w;
        }
#pragma unroll
        for (int i = 0; i < 2; i++) {
            int idx = tid + i * 256;
            int r = idx >> 3, c4 = idx & 7;
            float4 v = *(const float4*)&Wx[((size_t)(bn * 64 + r)) * 256 + kt + c4 * 4];
            Bs[c4 * 4 + 0][r] = v.x;
            Bs[c4 * 4 + 1][r] = v.y;
            Bs[c4 * 4 + 2][r] = v.z;
            Bs[c4 * 4 + 3][r] = v.w;
        }
        __syncthreads();
#pragma unroll
        for (int kk = 0; kk < 32; kk++) {
            float4 a0 = *(const float4*)&As[kk][ty * 8];
            float4 a1 = *(const float4*)&As[kk][ty * 8 + 4];
            float4 bv = *(const float4*)&Bs[kk][tx * 4];
            float av[8] = {a0.x, a0.y, a0.z, a0.w, a1.x, a1.y, a1.z, a1.w};
            float bvv[4] = {bv.x, bv.y, bv.z, bv.w};
#pragma unroll
            for (int i = 0; i < 8; i++)
#pragma unroll
                for (int j = 0; j < 4; j++) acc[i][j] += av[i] * bvv[j];
        }
        __syncthreads();
    }
#pragma unroll
    for (int i = 0; i < 8; i++) {
        int m = bm * 128 + ty * 8 + i;
#pragma unroll
        for (int j = 0; j < 4; j++) {
            int jj = bn * 64 + tx * 4 + j;
            g_P[(size_t)m * 256 + jj] = acc[i][j] + bx[jj] + bh[jj];
        }
    }
}

// -------- sentinel (placed so ncu's position-4 capture lands on k_scan) --------
__global__ void k_sent() {}

// -------- smem layout (float word offsets) --------
// Region0: phase A fp16 weights wh (16384 words) / phase B encS (34816 words)
#define OFF_HF   34816   // phase A sHF[2][256]
#define OFF_HB   35328   // phase A sHB[2][256]
#define OFF_H1   35840   // phase B sH own half (128)
#define OFF_H2   35968   // phase B sC own half (128)
#define OFF_RED  36096   // staging (2048)
#define OFF_AL   38144   // alpha (512)
#define OFF_SM   38656   // softmax scratch (64)
#define OFF_XB   38720   // phase B DSMEM ctx exchange (128)
#define OFF_XE   38848   // phase B DSMEM energy exchange (512)
#define OFF_MBA  39360   // phase A mbarrier (2 words)
#define OFF_MBB  39362   // phase B ctx mbarrier (2 words)
#define OFF_MBE  39364   // phase B energy mbarrier (2 words)
#define SMEM_FLTS 39368  // 157472 bytes

// -------- kernel 3: persistent scan (cluster of 2 per batch element) --------
__global__ void __launch_bounds__(NTH, 1) __cluster_dims__(2, 1, 1) k_scan() {
    extern __shared__ float smem[];
    const int cta = blockIdx.x;
    const int tid = threadIdx.x;
    const int b   = cta >> 1;
    const int jh  = cta & 1;
    const int lane = tid & 31;
    const int w    = tid >> 5;
    const int kq   = tid >> 7;      // 0..3
    const int j2   = tid & 127;

    __half2* wh = (__half2*)smem;            // phase A fp16 weights (k-pairs)
    __half2* encS2 = (__half2*)smem;         // phase B enc
    float* sHF  = smem + OFF_HF;
    float* sHB  = smem + OFF_HB;
    float* sH   = smem + OFF_H1;
    float* sC   = smem + OFF_H2;
    float* sRed = smem + OFF_RED;
    float* sAl  = smem + OFF_AL;
    float* sSm  = smem + OFF_SM;
    float* sXb  = smem + OFF_XB;
    float* sXe  = smem + OFF_XE;

    unsigned smem_base;
    asm("{ .reg .u64 t; cvta.to.shared.u64 t, %1; cvt.u32.u64 %0, t; }"
        : "=r"(smem_base) : "l"(smem));
    const unsigned mbarA = smem_base + OFF_MBA * 4;
    const unsigned mbarB = smem_base + OFF_MBB * 4;
    const unsigned mbarE = smem_base + OFF_MBE * 4;
    const unsigned peer = (unsigned)(jh ^ 1);

    if (tid == 0) {
        asm volatile("mbarrier.init.shared.b64 [%0], %1;" :: "r"(mbarA), "r"(256) : "memory");
        asm volatile("mbarrier.init.shared.b64 [%0], %1;" :: "r"(mbarB), "r"(128) : "memory");
        asm volatile("mbarrier.init.shared.b64 [%0], %1;" :: "r"(mbarE), "r"(512) : "memory");
    }
    __syncthreads();
    asm volatile("barrier.cluster.arrive.aligned;" ::: "memory");
    asm volatile("barrier.cluster.wait.aligned;" ::: "memory");

    // zero energy buffers 0,1 for this replay (buf2 zeroed by rotation); group = cta
    if (tid < 4) {
        g_e4[0][cta][tid] = 0.f;
        g_e4[1][cta][tid] = 0.f;
    }

    // ---------------- Phase A: j-split fwd+bwd scans, fp16 weights ----------------
    for (int i = tid; i < 16384; i += NTH) {
        int k2 = i >> 7, jj = i & 127;
        wh[i] = __floats2half2_rn(g_WhT[(2 * k2) * 256 + jh * 128 + jj],
                                  g_WhT[(2 * k2 + 1) * 256 + jh * 128 + jj]);
    }
    if (tid < 256) { sHF[tid] = 0.f; sHB[tid] = 0.f; }

    const int dirA = tid >> 7;     // meaningful for tid<256: 0 fwd, 1 bwd
    const int jxA  = tid & 127;
    const bool remoteK = ((kq >> 1) != jh);
    float cA = 0.f;

    unsigned rp0 = 0, rp1 = 0, r_mbA = 0, r_mbB = 0, r_mbE = 0, r_xb = 0, r_xe = 0;
    {
        unsigned base = (unsigned)(((tid >> 7) & 1 ? OFF_HB : OFF_HF) + jh * 128 + jxA);
        unsigned a0 = smem_base + base * 4;
        unsigned a1 = smem_base + (base + 256) * 4;
        asm("mapa.shared::cluster.u32 %0, %1, %2;" : "=r"(rp0) : "r"(a0), "r"(peer));
        asm("mapa.shared::cluster.u32 %0, %1, %2;" : "=r"(rp1) : "r"(a1), "r"(peer));
        asm("mapa.shared::cluster.u32 %0, %1, %2;" : "=r"(r_mbA) : "r"(mbarA), "r"(peer));
        asm("mapa.shared::cluster.u32 %0, %1, %2;" : "=r"(r_mbB) : "r"(mbarB), "r"(peer));
        asm("mapa.shared::cluster.u32 %0, %1, %2;" : "=r"(r_mbE) : "r"(mbarE), "r"(peer));
        unsigned l_xb = smem_base + (OFF_XB + jxA) * 4;
        asm("mapa.shared::cluster.u32 %0, %1, %2;" : "=r"(r_xb) : "r"(l_xb), "r"(peer));
        unsigned l_xe = smem_base + (OFF_XE + tid) * 4;
        asm("mapa.shared::cluster.u32 %0, %1, %2;" : "=r"(r_xe) : "r"(l_xe), "r"(peer));
    }
    __syncthreads();
    asm volatile("barrier.cluster.arrive.aligned;" ::: "memory");
    asm volatile("barrier.cluster.wait.aligned;" ::: "memory");

    for (int s = 0; s < Lz; s++) {
        const int cur = s & 1, nxt = cur ^ 1;
        float pf = 0.f;
        if (tid < 256) {
            int l = dirA ? (511 - s) : s;
            pf = __ldcg(&g_P[((size_t)l * 64 + b) * 256 + jh * 128 + jxA]);
        }
        if (remoteK && s) mbar_wait_cluster(mbarA, (unsigned)((s - 1) & 1));
        float af = 0.f, ab = 0.f;
        {
            const float4* hf4 = (const float4*)(sHF + cur * 256 + kq * 64);
            const float4* hb4 = (const float4*)(sHB + cur * 256 + kq * 64);
            const __half2* wp = wh + (kq * 32) * 128 + j2;
#pragma unroll
            for (int q = 0; q < 16; q++) {
                float4 hf = hf4[q], hb = hb4[q];
                float2 wa = __half22float2(wp[(2 * q) * 128]);
                float2 wb = __half22float2(wp[(2 * q + 1) * 128]);
                af += hf.x * wa.x + hf.y * wa.y + hf.z * wb.x + hf.w * wb.y;
                ab += hb.x * wa.x + hb.y * wa.y + hb.z * wb.x + hb.w * wb.y;
            }
        }
        sRed[kq * 128 + j2]       = af;
        sRed[512 + kq * 128 + j2] = ab;
        __syncthreads();
        if (tid < 256) {
            const float* rr = sRed + dirA * 512 + jxA;
            float pre = rr[0] + rr[128] + rr[256] + rr[384] + pf;
            float sg = fsig(pre), gg = ftanh(pre);
            cA = sg * (cA + gg);
            float hn = sg * ftanh(cA);
            (dirA ? sHB : sHF)[nxt * 256 + jh * 128 + jxA] = hn;
            unsigned r = nxt ? rp1 : rp0;
            asm volatile("st.shared::cluster.f32 [%0], %1;" :: "r"(r), "f"(hn) : "memory");
            asm volatile("mbarrier.arrive.release.cluster.shared::cluster.b64 _, [%0];"
                         :: "r"(r_mbA) : "memory");
        }
        __syncthreads();
        if (tid < 128)
            g_enc[((size_t)s * 64 + b) * 256 + jh * 128 + tid] =
                __float2half(0.5f * (sHF[nxt * 256 + jh * 128 + tid]
                                   + sHB[nxt * 256 + jh * 128 + tid]));
    }
    mbar_wait_cluster(mbarA, (unsigned)(511 & 1));

    // handover: bwd h/c into phase B state
    if (tid >= 128 && tid < 256) sRed[tid - 128] = cA;
    __syncthreads();
    float cB = 0.f;
    if (tid < 128) {
        sH[tid] = sHB[jh * 128 + tid];
        cB      = sRed[tid];
    }

    gbar();   // phase boundary

    // ---------------- Phase B prologue ----------------
    {
        const __half* gsrc = g_enc + (size_t)b * 256 + jh * 128;
#pragma unroll 4
        for (int i = 0; i < 32; i++) {
            int l = w * 32 + i;
            const uint2 v = *(const uint2*)(gsrc + (size_t)l * 16384 + lane * 4);
            unsigned* dst = ((unsigned*)smem) + (l * EPITCH + lane * 2);
            dst[0] = v.x; dst[1] = v.y;
        }
    }
    float wregL[32], wregR[32];
    {
        const float* wsL = g_WhT + (size_t)(jh * 128 + kq * 32) * 256 + jh * 128 + j2;
        const float* wsR = g_WhT + (size_t)((1 - jh) * 128 + kq * 32) * 256 + jh * 128 + j2;
#pragma unroll
        for (int i = 0; i < 32; i++) { wregL[i] = wsL[i * 256]; wregR[i] = wsR[i * 256]; }
    }
    __syncthreads();

    // ---------------- Phase B: 1 grid barrier + overlapped exchanges per step ----------------
    for (int t = 0; t < Lz; t++) {
        const int bufc = t % 3, bufz = (t + 2) % 3;

        // -- interval 1: energy partial for row l = tid --
        {
            float e = 0.f;
            const uint4* rp = (const uint4*)((const unsigned*)smem + tid * EPITCH);
            const float4* h4 = (const float4*)sH;
#pragma unroll 4
            for (int i = 0; i < 16; i++) {
                uint4 v = rp[i];
                float4 hA = h4[2 * i], hB = h4[2 * i + 1];
                float2 f0 = __half22float2(*(__half2*)&v.x);
                float2 f1 = __half22float2(*(__half2*)&v.y);
                float2 f2 = __half22float2(*(__half2*)&v.z);
                float2 f3 = __half22float2(*(__half2*)&v.w);
                e += f0.x * hA.x + f0.y * hA.y + f1.x * hA.z + f1.y * hA.w
                   + f2.x * hB.x + f2.y * hB.y + f3.x * hB.z + f3.y * hB.w;
            }
            if (jh == 1) {
                // push partial straight to partner + arrive; no RED from this CTA
                asm volatile("st.shared::cluster.f32 [%0], %1;" :: "r"(r_xe), "f"(e) : "memory");
                asm volatile("mbarrier.arrive.release.cluster.shared::cluster.b64 _, [%0];"
                             :: "r"(r_mbE) : "memory");
            } else {
                sRed[tid] = e;
            }
        }
        if (jh == 0) {
            __syncthreads();
            if (tid < 128) {
                mbar_wait_cluster(mbarE, (unsigned)(t & 1));
                float4 ev = *(const float4*)&sRed[tid * 4];
                float4 pv = *(const float4*)&sXe[tid * 4];
                asm volatile("red.global.add.v4.f32 [%0], {%1, %2, %3, %4};"
                             :: "l"(&g_e4[bufc][tid][0]),
                                "f"(ev.x + pv.x), "f"(ev.y + pv.y),
                                "f"(ev.z + pv.z), "f"(ev.w + pv.w) : "memory");
            }
        }
        unsigned long long tgt = 0;
        gbar_arrive(tgt);
        float pP = 0.f;
        if (tid < 128) pP = __ldcg(&g_P[((size_t)t * 64 + b) * 256 + jh * 128 + tid]);
        gbar_wait(tgt);

        // -- interval 2: softmax (replicated) --
        float myE = __ldcg(&g_e4[bufc][tid >> 2][tid & 3]);
        float m = myE;
#pragma unroll
        for (int o = 16; o > 0; o >>= 1) m = fmaxf(m, __shfl_xor_sync(0xffffffffu, m, o));
        if (lane == 0) sSm[w] = m;
        __syncthreads();
        float M = sSm[0];
#pragma unroll
        for (int ww = 1; ww < 16; ww++) M = fmaxf(M, sSm[ww]);
        float ex = __expf(myE - M);
        float ss = ex;
#pragma unroll
        for (int o = 16; o > 0; o >>= 1) ss += __shfl_xor_sync(0xffffffffu, ss, o);
        if (lane == 0) sSm[16 + w] = ss;
        __syncthreads();
        float tot = sSm[16];
#pragma unroll
        for (int ww = 1; ww < 16; ww++) tot += sSm[16 + ww];
        sAl[tid] = ex * __fdividef(1.f, tot);
        if (tid < 4) g_e4[bufz][cta][tid] = 0.f;   // zero buf t+2 (own group)
        __syncthreads();

        // -- context partial: thread (kp2 = tid&31 -> 8B col, lc = tid>>5 -> 32 l's) --
        {
            const int kp2 = tid & 31, lc = tid >> 5;
            const int l0 = lc * 32;
            float a0 = 0.f, a1 = 0.f, a2 = 0.f, a3 = 0.f;
            const float4* al4 = (const float4*)(sAl + l0);
            const unsigned* eb = (const unsigned*)smem;
#pragma unroll 4
            for (int q = 0; q < 8; q++) {
                float4 al = al4[q];
                int l = l0 + q * 4;
                uint2 v0 = *(const uint2*)(eb + (l + 0) * EPITCH + kp2 * 2);
                uint2 v1 = *(const uint2*)(eb + (l + 1) * EPITCH + kp2 * 2);
                uint2 v2 = *(const uint2*)(eb + (l + 2) * EPITCH + kp2 * 2);
                uint2 v3 = *(const uint2*)(eb + (l + 3) * EPITCH + kp2 * 2);
                float2 f;
                f = __half22float2(*(__half2*)&v0.x); a0 += al.x * f.x; a1 += al.x * f.y;
                f = __half22float2(*(__half2*)&v0.y); a2 += al.x * f.x; a3 += al.x * f.y;
                f = __half22float2(*(__half2*)&v1.x); a0 += al.y * f.x; a1 += al.y * f.y;
                f = __half22float2(*(__half2*)&v1.y); a2 += al.y * f.x; a3 += al.y * f.y;
                f = __half22float2(*(__half2*)&v2.x); a0 += al.z * f.x; a1 += al.z * f.y;
                f = __half22float2(*(__half2*)&v2.y); a2 += al.z * f.x; a3 += al.z * f.y;
                f = __half22float2(*(__half2*)&v3.x); a0 += al.w * f.x; a1 += al.w * f.y;
                f = __half22float2(*(__half2*)&v3.y); a2 += al.w * f.x; a3 += al.w * f.y;
            }
            float4* dst = (float4*)(sRed + lc * 128 + kp2 * 4);
            *dst = make_float4(a0, a1, a2, a3);
        }
        __syncthreads();
        if (tid < 128) {
            float cv = sH[tid];
#pragma unroll
            for (int lc = 0; lc < 16; lc++) cv += sRed[lc * 128 + tid];
            sC[tid] = cv;
            asm volatile("st.shared::cluster.f32 [%0], %1;" :: "r"(r_xb), "f"(cv) : "memory");
            asm volatile("mbarrier.arrive.release.cluster.shared::cluster.b64 _, [%0];"
                         :: "r"(r_mbB) : "memory");
        }
        __syncthreads();

        // -- matvec: local 32-k first, then remote 32-k after DSMEM wait --
        {
            float acc = 0.f;
            const float4* cL = (const float4*)(sC + kq * 32);
#pragma unroll
            for (int q = 0; q < 8; q++) {
                float4 cv = cL[q];
                acc += cv.x * wregL[q * 4]     + cv.y * wregL[q * 4 + 1]
                     + cv.z * wregL[q * 4 + 2] + cv.w * wregL[q * 4 + 3];
            }
            mbar_wait_cluster(mbarB, (unsigned)(t & 1));
            const float4* cR = (const float4*)(sXb + kq * 32);
#pragma unroll
            for (int q = 0; q < 8; q++) {
                float4 cv = cR[q];
                acc += cv.x * wregR[q * 4]     + cv.y * wregR[q * 4 + 1]
                     + cv.z * wregR[q * 4 + 2] + cv.w * wregR[q * 4 + 3];
            }
            sRed[kq * 128 + j2] = acc;
        }
        __syncthreads();

        // -- cell update on own j-half --
        if (tid < 128) {
            float pre = sRed[tid] + sRed[128 + tid] + sRed[256 + tid] + sRed[384 + tid] + pP;
            float sg = fsig(pre), gg = ftanh(pre);
            cB = sg * (cB + gg);
            float hn = sg * ftanh(cB);
            sH[tid] = hn;
            g_P[((size_t)t * 64 + b) * 256 + jh * 128 + tid] = hn;   // listH
        }
        __syncthreads();
    }

    asm volatile("barrier.cluster.arrive.aligned;" ::: "memory");
    asm volatile("barrier.cluster.wait.aligned;" ::: "memory");
}

// -------- kernel 4: out = listH@Wl^T + bl, mask --------
__global__ void k_proj(const float* __restrict__ Wl, const float* __restrict__ bl,
                       const int* __restrict__ slen, float* __restrict__ out) {
    int warp = blockIdx.x * (blockDim.x >> 5) + (threadIdx.x >> 5);
    int lane = threadIdx.x & 31;
    if (warp >= Bz * Lz) return;
    int b = warp >> 9, l = warp & 511;
    const float* hrow = g_P + ((size_t)l * 64 + b) * 256;
    float a0 = 0.f, a1 = 0.f;
#pragma unroll
    for (int i = 0; i < 8; i++) {
        float h = hrow[lane + 32 * i];
        a0 += h * Wl[lane + 32 * i];
        a1 += h * Wl[256 + lane + 32 * i];
    }
    for (int o = 16; o > 0; o >>= 1) {
        a0 += __shfl_down_sync(0xffffffffu, a0, o);
        a1 += __shfl_down_sync(0xffffffffu, a1, o);
    }
    if (lane == 0) {
        float o0 = a0 + bl[0];
        float o1 = a1 + bl[1];
        if (l > slen[b]) { o0 = 0.f; o1 = 1.f; }
        out[(size_t)warp * 2]     = o0;
        out[(size_t)warp * 2 + 1] = o1;
    }
}

// -------- host launcher --------
extern "C" void kernel_launch(void* const* d_in, const int* in_sizes, int n_in,
                              void* d_out, int out_size) {
    const float* x    = (const float*)d_in[0];
    const int*   slen = (const int*)  d_in[1];
    const float* Wh   = (const float*)d_in[2];
    const float* bh   = (const float*)d_in[3];
    const float* Wx   = (const float*)d_in[4];
    const float* bx   = (const float*)d_in[5];
    const float* Wl   = (const float*)d_in[6];
    const float* bl   = (const float*)d_in[7];
    float* out = (float*)d_out;

    const int smem_bytes = SMEM_FLTS * 4;
    cudaFuncSetAttribute(k_scan, cudaFuncAttributeMaxDynamicSharedMemorySize, smem_bytes);

    k_pre<<<256, 256>>>(Wh);
    k_gemm<<<dim3(4, 256), 256>>>(x, Wx, bx, bh);
    k_sent<<<1, 1>>>();
    k_scan<<<GRID, NTH, smem_bytes>>>();
    k_proj<<<4096, 256>>>(Wl, bl, slen, out);
}

// round 16
// speedup vs baseline: 1.0474x; 1.0474x over previous
#include <cuda_runtime.h>
#include <cuda_fp16.h>
#include <math.h>

// Problem constants
#define Bz   64
#define Lz   512
#define Hz   256
#define GRID 128
#define NTH  512

#define EPITCH 68   // enc smem pitch in 4-byte words (272B rows, conflict-free)

// -------- device scratch --------
__device__ float  g_P[Lz * Bz * Hz];       // P / listH
__device__ __half g_enc[Lz * Bz * Hz];     // enc fp16 (CTA-local round trip)
__device__ float  g_WhT[Hz * Hz];          // WhT[k*256+j]
__device__ float  g_e4[3][128][32];        // energies: 128 groups of 4 l's, 128B stride, 3 bufs
__device__ unsigned long long g_l1[16 * 16];  // barrier level-1 counters (padded)
__device__ unsigned long long g_root = 0;     // barrier root counter

// -------- fast transcendentals (MUFU-based, ~2 ulp) --------
__device__ __forceinline__ float fsig(float x) {
    return __fdividef(1.f, 1.f + __expf(-x));
}
__device__ __forceinline__ float ftanh(float x) {
    return 1.f - __fdividef(2.f, __expf(2.f * x) + 1.f);
}

// -------- two-level grid barrier, split arrive/wait (monotonic) --------
__device__ __forceinline__ void gbar_arrive(unsigned long long& target) {
    __syncthreads();
    if (threadIdx.x == 0) {
        __threadfence();   // release (drains this CTA's RED/STG)
        unsigned long long a = atomicAdd(&g_l1[(blockIdx.x & 15) * 16], 1ULL);
        if ((a & 7ULL) == 7ULL) atomicAdd(&g_root, 1ULL);
        target = ((a >> 3) + 1ULL) * 16ULL;
    }
}
__device__ __forceinline__ void gbar_wait(unsigned long long target) {
    if (threadIdx.x == 0) {
        while (*((volatile unsigned long long*)&g_root) < target) { }
        __threadfence();   // acquire
    }
    __syncthreads();
}
__device__ __forceinline__ void gbar() {
    unsigned long long tgt = 0;
    gbar_arrive(tgt);
    gbar_wait(tgt);
}

// -------- cluster-scope mbarrier parity wait (acquire.cluster) --------
__device__ __forceinline__ void mbar_wait_cluster(unsigned mbar, unsigned parity) {
    unsigned done;
    do {
        asm volatile(
            "{\n\t.reg .pred p;\n\t"
            "mbarrier.try_wait.parity.acquire.cluster.shared::cta.b64 p, [%1], %2;\n\t"
            "selp.b32 %0, 1, 0, p;\n\t}"
            : "=r"(done) : "r"(mbar), "r"(parity) : "memory");
    } while (!done);
}

// -------- kernel 1: transpose Wh --------
__global__ void k_pre(const float* __restrict__ Wh) {
    int t = blockIdx.x * 256 + threadIdx.x;
    if (t < Hz * Hz) {
        int j = t >> 8, k = t & 255;
        g_WhT[k * 256 + j] = Wh[j * 256 + k];
    }
}

// -------- kernel 2: P = x@Wx^T + bx + bh  (128x64 tile, 8x4/thread) --------
__global__ void k_gemm(const float* __restrict__ x, const float* __restrict__ Wx,
                       const float* __restrict__ bx, const float* __restrict__ bh) {
    __shared__ float As[32][132];
    __shared__ float Bs[32][68];
    const int bm = blockIdx.y;
    const int bn = blockIdx.x;
    const int tid = threadIdx.x;
    const int ty = tid >> 4, tx = tid & 15;

    float acc[8][4];
#pragma unroll
    for (int i = 0; i < 8; i++)
#pragma unroll
        for (int j = 0; j < 4; j++) acc[i][j] = 0.f;

    for (int kt = 0; kt < 256; kt += 32) {
#pragma unroll
        for (int i = 0; i < 4; i++) {
            int idx = tid + i * 256;
            int r = idx >> 3, c4 = idx & 7;
            int m = bm * 128 + r;
            int l = m >> 6, b = m & 63;
            float4 v = *(const float4*)&x[((size_t)b * 512 + l) * 256 + kt + c4 * 4];
            As[c4 * 4 + 0][r] = v.x;
            As[c4 * 4 + 1][r] = v.y;
            As[c4 * 4 + 2][r] = v.z;
            As[c4 * 4 + 3][r] = v.w;
        }
#pragma unroll
        for (int i = 0; i < 2; i++) {
            int idx = tid + i * 256;
            int r = idx >> 3, c4 = idx & 7;
            float4 v = *(const float4*)&Wx[((size_t)(bn * 64 + r)) * 256 + kt + c4 * 4];
            Bs[c4 * 4 + 0][r] = v.x;
            Bs[c4 * 4 + 1][r] = v.y;
            Bs[c4 * 4 + 2][r] = v.z;
            Bs[c4 * 4 + 3][r] = v.w;
        }
        __syncthreads();
#pragma unroll
        for (int kk = 0; kk < 32; kk++) {
            float4 a0 = *(const float4*)&As[kk][ty * 8];
            float4 a1 = *(const float4*)&As[kk][ty * 8 + 4];
            float4 bv = *(const float4*)&Bs[kk][tx * 4];
            float av[8] = {a0.x, a0.y, a0.z, a0.w, a1.x, a1.y, a1.z, a1.w};
            float bvv[4] = {bv.x, bv.y, bv.z, bv.w};
#pragma unroll
            for (int i = 0; i < 8; i++)
#pragma unroll
                for (int j = 0; j < 4; j++) acc[i][j] += av[i] * bvv[j];
        }
        __syncthreads();
    }
#pragma unroll
    for (int i = 0; i < 8; i++) {
        int m = bm * 128 + ty * 8 + i;
#pragma unroll
        for (int j = 0; j < 4; j++) {
            int jj = bn * 64 + tx * 4 + j;
            g_P[(size_t)m * 256 + jj] = acc[i][j] + bx[jj] + bh[jj];
        }
    }
}

// -------- sentinel (so ncu's capture slot lands on k_scan) --------
__global__ void k_sent() {}

// -------- smem layout (float word offsets) --------
// Region0: phase A fp16 weights wh (16384 words) / phase B encS (34816 words)
#define OFF_HF   34816   // phase A sHF[2][256]
#define OFF_HB   35328   // phase A sHB[2][256]
#define OFF_H1   35840   // phase B sH own half (128)
#define OFF_H2   35968   // phase B sC own half (128)
#define OFF_RED  36096   // staging (2048)
#define OFF_AL   38144   // alpha (512)
#define OFF_SM   38656   // softmax scratch (64)
#define OFF_XB   38720   // phase B DSMEM exchange (128)
#define OFF_MBA  38848   // phase A mbarrier (2 words)
#define OFF_MBB  38850   // phase B mbarrier (2 words)
#define SMEM_FLTS 38852  // 155408 bytes

// -------- kernel 3: persistent scan (cluster of 2 per batch element) --------
__global__ void __launch_bounds__(NTH, 1) __cluster_dims__(2, 1, 1) k_scan() {
    extern __shared__ float smem[];
    const int cta = blockIdx.x;
    const int tid = threadIdx.x;
    const int b   = cta >> 1;
    const int jh  = cta & 1;
    const int lane = tid & 31;
    const int w    = tid >> 5;
    const int kq   = tid >> 7;      // phase B: 0..3
    const int j2   = tid & 127;     // phase B
    const int ko   = tid >> 6;      // phase A: 0..7 (k-group of 32)
    const int jp   = tid & 63;      // phase A: j columns {jp, jp+64}

    __half2* wh = (__half2*)smem;            // phase A fp16 weights (k-pairs)
    __half2* encS2 = (__half2*)smem;         // phase B enc
    float* sHF  = smem + OFF_HF;
    float* sHB  = smem + OFF_HB;
    float* sH   = smem + OFF_H1;
    float* sC   = smem + OFF_H2;
    float* sRed = smem + OFF_RED;
    float* sAl  = smem + OFF_AL;
    float* sSm  = smem + OFF_SM;
    float* sXb  = smem + OFF_XB;

    unsigned smem_base;
    asm("{ .reg .u64 t; cvta.to.shared.u64 t, %1; cvt.u32.u64 %0, t; }"
        : "=r"(smem_base) : "l"(smem));
    const unsigned mbarA = smem_base + OFF_MBA * 4;
    const unsigned mbarB = smem_base + OFF_MBB * 4;
    const unsigned peer = (unsigned)(jh ^ 1);

    if (tid == 0) {
        asm volatile("mbarrier.init.shared.b64 [%0], %1;" :: "r"(mbarA), "r"(256) : "memory");
        asm volatile("mbarrier.init.shared.b64 [%0], %1;" :: "r"(mbarB), "r"(128) : "memory");
    }
    __syncthreads();
    asm volatile("barrier.cluster.arrive.aligned;" ::: "memory");
    asm volatile("barrier.cluster.wait.aligned;" ::: "memory");

    // zero energy buffers 0,1 for this replay (buf2 zeroed by rotation); group = cta
    if (tid < 4) {
        g_e4[0][cta][tid] = 0.f;
        g_e4[1][cta][tid] = 0.f;
    }

    // ---------------- Phase A: j-split fwd+bwd scans, fp16 weights ----------------
    for (int i = tid; i < 16384; i += NTH) {
        int k2 = i >> 7, jj = i & 127;
        wh[i] = __floats2half2_rn(g_WhT[(2 * k2) * 256 + jh * 128 + jj],
                                  g_WhT[(2 * k2 + 1) * 256 + jh * 128 + jj]);
    }
    if (tid < 256) { sHF[tid] = 0.f; sHB[tid] = 0.f; }

    const int dirA = tid >> 7;     // meaningful for tid<256: 0 fwd, 1 bwd
    const int jxA  = tid & 127;
    const bool remoteK = ((ko >> 2) != jh);   // k-range [ko*32,+32) in partner's h-half?
    float cA = 0.f;

    unsigned rp0 = 0, rp1 = 0, r_mbA = 0, r_mbB = 0, r_xb = 0;
    {
        unsigned base = (unsigned)(((tid >> 7) & 1 ? OFF_HB : OFF_HF) + jh * 128 + jxA);
        unsigned a0 = smem_base + base * 4;
        unsigned a1 = smem_base + (base + 256) * 4;
        asm("mapa.shared::cluster.u32 %0, %1, %2;" : "=r"(rp0) : "r"(a0), "r"(peer));
        asm("mapa.shared::cluster.u32 %0, %1, %2;" : "=r"(rp1) : "r"(a1), "r"(peer));
        asm("mapa.shared::cluster.u32 %0, %1, %2;" : "=r"(r_mbA) : "r"(mbarA), "r"(peer));
        asm("mapa.shared::cluster.u32 %0, %1, %2;" : "=r"(r_mbB) : "r"(mbarB), "r"(peer));
        unsigned l_xb = smem_base + (OFF_XB + jxA) * 4;
        asm("mapa.shared::cluster.u32 %0, %1, %2;" : "=r"(r_xb) : "r"(l_xb), "r"(peer));
    }
    __syncthreads();
    asm volatile("barrier.cluster.arrive.aligned;" ::: "memory");
    asm volatile("barrier.cluster.wait.aligned;" ::: "memory");

    for (int s = 0; s < Lz; s++) {
        const int cur = s & 1, nxt = cur ^ 1;
        float pf = 0.f;
        if (tid < 256) {
            int l = dirA ? (511 - s) : s;
            pf = __ldcg(&g_P[((size_t)l * 64 + b) * 256 + jh * 128 + jxA]);
        }
        if (remoteK && s) mbar_wait_cluster(mbarA, (unsigned)((s - 1) & 1));
        // matvec: thread (ko, jp) covers k in [ko*32, ko*32+32), j in {jp, jp+64}
        float af0 = 0.f, ab0 = 0.f, af1 = 0.f, ab1 = 0.f;
        {
            const float4* hf4 = (const float4*)(sHF + cur * 256 + ko * 32);
            const float4* hb4 = (const float4*)(sHB + cur * 256 + ko * 32);
            const __half2* wp = wh + (ko * 16) * 128 + jp;
#pragma unroll
            for (int q = 0; q < 8; q++) {
                float4 hf = hf4[q], hb = hb4[q];
                float2 wA0 = __half22float2(wp[(2 * q) * 128]);
                float2 wB0 = __half22float2(wp[(2 * q + 1) * 128]);
                float2 wA1 = __half22float2(wp[(2 * q) * 128 + 64]);
                float2 wB1 = __half22float2(wp[(2 * q + 1) * 128 + 64]);
                af0 += hf.x * wA0.x + hf.y * wA0.y + hf.z * wB0.x + hf.w * wB0.y;
                ab0 += hb.x * wA0.x + hb.y * wA0.y + hb.z * wB0.x + hb.w * wB0.y;
                af1 += hf.x * wA1.x + hf.y * wA1.y + hf.z * wB1.x + hf.w * wB1.y;
                ab1 += hb.x * wA1.x + hb.y * wA1.y + hb.z * wB1.x + hb.w * wB1.y;
            }
        }
        sRed[ko * 128 + jp]             = af0;
        sRed[ko * 128 + 64 + jp]        = af1;
        sRed[1024 + ko * 128 + jp]      = ab0;
        sRed[1024 + ko * 128 + 64 + jp] = ab1;
        __syncthreads();
        if (tid < 256) {
            const float* rr = sRed + dirA * 1024 + jxA;
            float pre = rr[0] + rr[128] + rr[256] + rr[384]
                      + rr[512] + rr[640] + rr[768] + rr[896] + pf;
            float sg = fsig(pre), gg = ftanh(pre);
            cA = sg * (cA + gg);
            float hn = sg * ftanh(cA);
            (dirA ? sHB : sHF)[nxt * 256 + jh * 128 + jxA] = hn;
            unsigned r = nxt ? rp1 : rp0;
            asm volatile("st.shared::cluster.f32 [%0], %1;" :: "r"(r), "f"(hn) : "memory");
            asm volatile("mbarrier.arrive.release.cluster.shared::cluster.b64 _, [%0];"
                         :: "r"(r_mbA) : "memory");
        }
        __syncthreads();
        if (tid < 128)
            g_enc[((size_t)s * 64 + b) * 256 + jh * 128 + tid] =
                __float2half(0.5f * (sHF[nxt * 256 + jh * 128 + tid]
                                   + sHB[nxt * 256 + jh * 128 + tid]));
    }
    mbar_wait_cluster(mbarA, (unsigned)(511 & 1));

    // handover: bwd h/c into phase B state
    if (tid >= 128 && tid < 256) sRed[tid - 128] = cA;
    __syncthreads();
    float cB = 0.f;
    if (tid < 128) {
        sH[tid] = sHB[jh * 128 + tid];
        cB      = sRed[tid];
    }

    gbar();   // phase boundary

    // ---------------- Phase B prologue ----------------
    {
        const __half* gsrc = g_enc + (size_t)b * 256 + jh * 128;
#pragma unroll 4
        for (int i = 0; i < 32; i++) {
            int l = w * 32 + i;
            const uint2 v = *(const uint2*)(gsrc + (size_t)l * 16384 + lane * 4);
            unsigned* dst = ((unsigned*)smem) + (l * EPITCH + lane * 2);
            dst[0] = v.x; dst[1] = v.y;
        }
    }
    float wregL[32], wregR[32];
    {
        const float* wsL = g_WhT + (size_t)(jh * 128 + kq * 32) * 256 + jh * 128 + j2;
        const float* wsR = g_WhT + (size_t)((1 - jh) * 128 + kq * 32) * 256 + jh * 128 + j2;
#pragma unroll
        for (int i = 0; i < 32; i++) { wregL[i] = wsL[i * 256]; wregR[i] = wsR[i * 256]; }
    }
    __syncthreads();

    // ---------------- Phase B: 1 grid barrier + overlapped ctx exchange per step ----------------
    for (int t = 0; t < Lz; t++) {
        const int bufc = t % 3, bufz = (t + 2) % 3;

        // -- interval 1: energy partial for row l = tid; vector RED --
        {
            float e = 0.f;
            const uint4* rp = (const uint4*)((const unsigned*)smem + tid * EPITCH);
            const float4* h4 = (const float4*)sH;
#pragma unroll 4
            for (int i = 0; i < 16; i++) {
                uint4 v = rp[i];
                float4 hA = h4[2 * i], hB = h4[2 * i + 1];
                float2 f0 = __half22float2(*(__half2*)&v.x);
                float2 f1 = __half22float2(*(__half2*)&v.y);
                float2 f2 = __half22float2(*(__half2*)&v.z);
                float2 f3 = __half22float2(*(__half2*)&v.w);
                e += f0.x * hA.x + f0.y * hA.y + f1.x * hA.z + f1.y * hA.w
                   + f2.x * hB.x + f2.y * hB.y + f3.x * hB.z + f3.y * hB.w;
            }
            sRed[tid] = e;
        }
        __syncthreads();
        if (tid < 128) {
            float4 ev = *(const float4*)&sRed[tid * 4];
            asm volatile("red.global.add.v4.f32 [%0], {%1, %2, %3, %4};"
                         :: "l"(&g_e4[bufc][tid][0]),
                            "f"(ev.x), "f"(ev.y), "f"(ev.z), "f"(ev.w) : "memory");
        }
        unsigned long long tgt = 0;
        gbar_arrive(tgt);
        float pP = 0.f;
        if (tid < 128) pP = __ldcg(&g_P[((size_t)t * 64 + b) * 256 + jh * 128 + tid]);
        gbar_wait(tgt);

        // -- interval 2: softmax (warp (m,s) pairs, warp0 combine) --
        float myE = __ldcg(&g_e4[bufc][tid >> 2][tid & 3]);
        float m = myE;
#pragma unroll
        for (int o = 16; o > 0; o >>= 1) m = fmaxf(m, __shfl_xor_sync(0xffffffffu, m, o));
        float ex = __expf(myE - m);       // own-warp max subtracted
        float ss = ex;
#pragma unroll
        for (int o = 16; o > 0; o >>= 1) ss += __shfl_xor_sync(0xffffffffu, ss, o);
        if (lane == 0) { sSm[w] = m; sSm[16 + w] = ss; }
        __syncthreads();
        if (w == 0) {
            int ww = lane & 15;
            float mw = sSm[ww], sw = sSm[16 + ww];
            float M = mw;
#pragma unroll
            for (int o = 8; o > 0; o >>= 1) M = fmaxf(M, __shfl_xor_sync(0xffffffffu, M, o));
            float g = __expf(mw - M);
            float p = sw * g;
#pragma unroll
            for (int o = 8; o > 0; o >>= 1) p += __shfl_xor_sync(0xffffffffu, p, o);
            if (lane < 16) sSm[32 + lane] = g * __fdividef(1.f, p);
        }
        __syncthreads();
        sAl[tid] = ex * sSm[32 + w];
        if (tid < 4) g_e4[bufz][cta][tid] = 0.f;   // zero buf t+2 (own group)
        __syncthreads();

        // -- context partial: thread (kp2 = tid&31 -> 8B col, lc = tid>>5 -> 32 l's) --
        {
            const int kp2 = tid & 31, lc = tid >> 5;
            const int l0 = lc * 32;
            float a0 = 0.f, a1 = 0.f, a2 = 0.f, a3 = 0.f;
            const float4* al4 = (const float4*)(sAl + l0);
            const unsigned* eb = (const unsigned*)smem;
#pragma unroll 4
            for (int q = 0; q < 8; q++) {
                float4 al = al4[q];
                int l = l0 + q * 4;
                uint2 v0 = *(const uint2*)(eb + (l + 0) * EPITCH + kp2 * 2);
                uint2 v1 = *(const uint2*)(eb + (l + 1) * EPITCH + kp2 * 2);
                uint2 v2 = *(const uint2*)(eb + (l + 2) * EPITCH + kp2 * 2);
                uint2 v3 = *(const uint2*)(eb + (l + 3) * EPITCH + kp2 * 2);
                float2 f;
                f = __half22float2(*(__half2*)&v0.x); a0 += al.x * f.x; a1 += al.x * f.y;
                f = __half22float2(*(__half2*)&v0.y); a2 += al.x * f.x; a3 += al.x * f.y;
                f = __half22float2(*(__half2*)&v1.x); a0 += al.y * f.x; a1 += al.y * f.y;
                f = __half22float2(*(__half2*)&v1.y); a2 += al.y * f.x; a3 += al.y * f.y;
                f = __half22float2(*(__half2*)&v2.x); a0 += al.z * f.x; a1 += al.z * f.y;
                f = __half22float2(*(__half2*)&v2.y); a2 += al.z * f.x; a3 += al.z * f.y;
                f = __half22float2(*(__half2*)&v3.x); a0 += al.w * f.x; a1 += al.w * f.y;
                f = __half22float2(*(__half2*)&v3.y); a2 += al.w * f.x; a3 += al.w * f.y;
            }
            float4* dst = (float4*)(sRed + lc * 128 + kp2 * 4);
            *dst = make_float4(a0, a1, a2, a3);
        }
        __syncthreads();
        if (tid < 128) {
            float cv = sH[tid];
#pragma unroll
            for (int lc = 0; lc < 16; lc++) cv += sRed[lc * 128 + tid];
            sC[tid] = cv;
            asm volatile("st.shared::cluster.f32 [%0], %1;" :: "r"(r_xb), "f"(cv) : "memory");
            asm volatile("mbarrier.arrive.release.cluster.shared::cluster.b64 _, [%0];"
                         :: "r"(r_mbB) : "memory");
        }
        __syncthreads();

        // -- matvec: local 32-k first, then remote 32-k after DSMEM wait --
        {
            float acc = 0.f;
            const float4* cL = (const float4*)(sC + kq * 32);
#pragma unroll
            for (int q = 0; q < 8; q++) {
                float4 cv = cL[q];
                acc += cv.x * wregL[q * 4]     + cv.y * wregL[q * 4 + 1]
                     + cv.z * wregL[q * 4 + 2] + cv.w * wregL[q * 4 + 3];
            }
            mbar_wait_cluster(mbarB, (unsigned)(t & 1));
            const float4* cR = (const float4*)(sXb + kq * 32);
#pragma unroll
            for (int q = 0; q < 8; q++) {
                float4 cv = cR[q];
                acc += cv.x * wregR[q * 4]     + cv.y * wregR[q * 4 + 1]
                     + cv.z * wregR[q * 4 + 2] + cv.w * wregR[q * 4 + 3];
            }
            sRed[kq * 128 + j2] = acc;
        }
        __syncthreads();

        // -- cell update on own j-half --
        if (tid < 128) {
            float pre = sRed[tid] + sRed[128 + tid] + sRed[256 + tid] + sRed[384 + tid] + pP;
            float sg = fsig(pre), gg = ftanh(pre);
            cB = sg * (cB + gg);
            float hn = sg * ftanh(cB);
            sH[tid] = hn;
            g_P[((size_t)t * 64 + b) * 256 + jh * 128 + tid] = hn;   // listH
        }
        __syncthreads();
    }

    asm volatile("barrier.cluster.arrive.aligned;" ::: "memory");
    asm volatile("barrier.cluster.wait.aligned;" ::: "memory");
}

// -------- kernel 4: out = listH@Wl^T + bl, mask --------
__global__ void k_proj(const float* __restrict__ Wl, const float* __restrict__ bl,
                       const int* __restrict__ slen, float* __restrict__ out) {
    int warp = blockIdx.x * (blockDim.x >> 5) + (threadIdx.x >> 5);
    int lane = threadIdx.x & 31;
    if (warp >= Bz * Lz) return;
    int b = warp >> 9, l = warp & 511;
    const float* hrow = g_P + ((size_t)l * 64 + b) * 256;
    float a0 = 0.f, a1 = 0.f;
#pragma unroll
    for (int i = 0; i < 8; i++) {
        float h = hrow[lane + 32 * i];
        a0 += h * Wl[lane + 32 * i];
        a1 += h * Wl[256 + lane + 32 * i];
    }
    for (int o = 16; o > 0; o >>= 1) {
        a0 += __shfl_down_sync(0xffffffffu, a0, o);
        a1 += __shfl_down_sync(0xffffffffu, a1, o);
    }
    if (lane == 0) {
        float o0 = a0 + bl[0];
        float o1 = a1 + bl[1];
        if (l > slen[b]) { o0 = 0.f; o1 = 1.f; }
        out[(size_t)warp * 2]     = o0;
        out[(size_t)warp * 2 + 1] = o1;
    }
}

// -------- host launcher --------
extern "C" void kernel_launch(void* const* d_in, const int* in_sizes, int n_in,
                              void* d_out, int out_size) {
    const float* x    = (const float*)d_in[0];
    const int*   slen = (const int*)  d_in[1];
    const float* Wh   = (const float*)d_in[2];
    const float* bh   = (const float*)d_in[3];
    const float* Wx   = (const float*)d_in[4];
    const float* bx   = (const float*)d_in[5];
    const float* Wl   = (const float*)d_in[6];
    const float* bl   = (const float*)d_in[7];
    float* out = (float*)d_out;

    const int smem_bytes = SMEM_FLTS * 4;
    cudaFuncSetAttribute(k_scan, cudaFuncAttributeMaxDynamicSharedMemorySize, smem_bytes);

    k_pre<<<256, 256>>>(Wh);
    k_gemm<<<dim3(4, 256), 256>>>(x, Wx, bx, bh);
    k_sent<<<1, 1>>>();
    k_scan<<<GRID, NTH, smem_bytes>>>();
    k_proj<<<4096, 256>>>(Wl, bl, slen, out);
}